// round 17
// baseline (speedup 1.0000x reference)
#include <cuda_runtime.h>
#include <math.h>

// ---------------------------------------------------------------------------
// ProteinEmbeddingPooling — R14 8-launch skeleton (76.3us best), one change:
// attn uses a cp.async (LDGSTS) smem ring, DEPTH=3 rows in flight per warp.
// In-flight data moves from registers to smem -> deep pipeline w/o spills.
// ---------------------------------------------------------------------------

#define BB 32
#define SS 1024
#define DD 1280
#define CTAS_PER_B 16
#define WPB 4
#define NCP CTAS_PER_B                   // attn partials per batch
#define RPW (SS / (CTAS_PER_B * WPB))    // 16 rows per warp
#define DEPTH 3                          // cp.async ring depth (rows/warp)

// dynamic smem layout (floats): skq[1280] | ring[4*DEPTH*1280] | sacc[4*1280]
#define SMEM_ATTN ((DD + WPB * DEPTH * DD + WPB * DD) * 4)

// ---- scratch (device globals; no allocation allowed) ----
__device__ float g_q0[BB * DD];
__device__ float g_kq[BB * DD];
__device__ float g_ctx[BB * DD];
__device__ float g_h[BB * DD];
__device__ float g_pm[BB * NCP];
__device__ float g_pl[BB * NCP];
__device__ float g_pacc[(size_t)BB * NCP * DD];      // 2.6 MB
__device__ float g_pooled[BB * DD];

__device__ __forceinline__ void red_add_v4(float* p, float a, float b,
                                           float c, float d)
{
    asm volatile("red.global.add.v4.f32 [%0], {%1, %2, %3, %4};"
                 :: "l"(p), "f"(a), "f"(b), "f"(c), "f"(d) : "memory");
}

__device__ __forceinline__ void cp_async16(void* smem_dst, const void* gmem_src)
{
    unsigned s = (unsigned)__cvta_generic_to_shared(smem_dst);
    asm volatile("cp.async.cg.shared.global [%0], [%1], 16;"
                 :: "r"(s), "l"(gmem_src));
}

// ---------------------------------------------------------------------------
// init: C matrices start at their bias (gemm RED partials accumulate on top)
// ---------------------------------------------------------------------------
__global__ void init_kernel(const float* __restrict__ bq,
                            const float* __restrict__ bv,
                            const float* __restrict__ bo)
{
    int i = blockIdx.x * blockDim.x + threadIdx.x;
    if (i < BB * DD) {
        int n = i % DD;
        g_q0[i]  = bq[n];
        g_kq[i]  = 0.0f;
        g_ctx[i] = bv[n];
        g_h[i]   = bo[n];
    }
}

// ---------------------------------------------------------------------------
// small GEMM: C[32,1280] += A[32,1280] * op(W)   (R14-exact: 4m x 4n tile)
// grid (20, 32), block 128. Epilogue: red.global.add.v4.f32 x4 per thread.
// ---------------------------------------------------------------------------
template<int MODE, int SRC, int DST>
__global__ void __launch_bounds__(128) gemm32(const float* __restrict__ Aext,
                                              size_t lda,
                                              const float* __restrict__ W)
{
    constexpr int NT = 64;
    constexpr int KC = 40;

    const float* A = (SRC == 0) ? Aext
                   : (SRC == 1) ? g_q0
                   : (SRC == 2) ? g_pooled
                   :              g_ctx;
    if (SRC != 0) lda = DD;
    float* C = (DST == 0) ? g_q0
             : (DST == 1) ? g_kq
             : (DST == 2) ? g_ctx
             :              g_h;

    __shared__ float As[KC][33];     // [k][m]
    __shared__ float Ws[KC][68];     // [k][n]

    const int tid = threadIdx.x;     // 0..127
    const int n0 = blockIdx.x * NT;
    const int k0 = blockIdx.y * KC;
    const int k04 = k0 >> 2;

    const float4* A4 = reinterpret_cast<const float4*>(A);
    const size_t lda4 = lda >> 2;
#pragma unroll
    for (int i = 0; i < 3; i++) {
        int f = tid + i * 128;
        if (f < 320) {
            int m = f / 10, kc4 = f % 10;
            float4 v = A4[(size_t)m * lda4 + k04 + kc4];
            As[kc4 * 4 + 0][m] = v.x;
            As[kc4 * 4 + 1][m] = v.y;
            As[kc4 * 4 + 2][m] = v.z;
            As[kc4 * 4 + 3][m] = v.w;
        }
    }

    const float4* W4 = reinterpret_cast<const float4*>(W);
    if (MODE == 1) {
#pragma unroll
        for (int i = 0; i < 5; i++) {
            int f = tid + i * 128;       // 0..639
            int kr = f >> 4, nc = f & 15;
            float4 v = W4[(size_t)(k0 + kr) * (DD / 4) + (n0 >> 2) + nc];
            reinterpret_cast<float4*>(&Ws[kr][0])[nc] = v;
        }
    } else {
#pragma unroll
        for (int i = 0; i < 5; i++) {
            int f = tid + i * 128;
            int n = f / 10, kc4 = f % 10;
            float4 v = W4[(size_t)(n0 + n) * (DD / 4) + k04 + kc4];
            Ws[kc4 * 4 + 0][n] = v.x;
            Ws[kc4 * 4 + 1][n] = v.y;
            Ws[kc4 * 4 + 2][n] = v.z;
            Ws[kc4 * 4 + 3][n] = v.w;
        }
    }
    __syncthreads();

    const int tx = tid & 15;
    const int ty = tid >> 4;             // 0..7

    float acc[4][4] = {};
#pragma unroll 8
    for (int k = 0; k < KC; k++) {
        float a[4];
#pragma unroll
        for (int i = 0; i < 4; i++) a[i] = As[k][ty + 8 * i];
        const float4 w = reinterpret_cast<const float4*>(&Ws[k][0])[tx];
#pragma unroll
        for (int i = 0; i < 4; i++) {
            acc[i][0] = fmaf(a[i], w.x, acc[i][0]);
            acc[i][1] = fmaf(a[i], w.y, acc[i][1]);
            acc[i][2] = fmaf(a[i], w.z, acc[i][2]);
            acc[i][3] = fmaf(a[i], w.w, acc[i][3]);
        }
    }

#pragma unroll
    for (int i = 0; i < 4; i++)
        red_add_v4(&C[(size_t)(ty + 8 * i) * DD + n0 + tx * 4],
                   acc[i][0], acc[i][1], acc[i][2], acc[i][3]);
}

// ---------------------------------------------------------------------------
// attention + pooling — cp.async ring pipeline (DEPTH=3 rows/warp in smem).
// grid 512 (32 b x 16 CTAs), block 128 (4 warps x 16 rows). kq in registers.
// ---------------------------------------------------------------------------
__global__ void __launch_bounds__(128) attn_kernel(const float* __restrict__ emb,
                                                   const int* __restrict__ mask,
                                                   const float* __restrict__ bk,
                                                   float scale)
{
    extern __shared__ float dsm[];
    float*  skq  = dsm;                                    // [DD]
    float4* ring = reinterpret_cast<float4*>(dsm + DD);    // [4*DEPTH*320]
    float4* sacc = reinterpret_cast<float4*>(dsm + DD + WPB * DEPTH * DD);
    __shared__ float sm[WPB], sl[WPB], scb;

    const int b = blockIdx.x / CTAS_PER_B;
    const int cta = blockIdx.x % CTAS_PER_B;
    const int tid = threadIdx.x;
    const int warp = tid >> 5;
    const int lane = tid & 31;
    const int split = cta * WPB + warp;
    const int s0 = split * RPW;

    // kq -> smem -> registers
    {
        const float4* src = reinterpret_cast<const float4*>(g_kq + b * DD);
        float4* dst = reinterpret_cast<float4*>(skq);
        for (int i = tid; i < DD / 4; i += 128) dst[i] = src[i];
    }
    if (warp == 0) {
        const float4* q04 = reinterpret_cast<const float4*>(g_q0 + b * DD);
        const float4* bk4 = reinterpret_cast<const float4*>(bk);
        float p = 0.0f;
#pragma unroll
        for (int c = 0; c < 10; c++) {
            const float4 q = q04[c * 32 + lane];
            const float4 k = bk4[c * 32 + lane];
            p = fmaf(q.x, k.x, p); p = fmaf(q.y, k.y, p);
            p = fmaf(q.z, k.z, p); p = fmaf(q.w, k.w, p);
        }
#pragma unroll
        for (int off = 16; off > 0; off >>= 1)
            p += __shfl_xor_sync(0xffffffffu, p, off);
        if (lane == 0) scb = p;
    }

    const float4* base4 =
        reinterpret_cast<const float4*>(emb + (size_t)b * SS * DD);
    float4* myring = ring + (size_t)warp * DEPTH * (DD / 4);

    // prologue: issue rows s0 .. s0+DEPTH-1
#pragma unroll
    for (int d = 0; d < DEPTH; d++) {
        const float4* src = base4 + (size_t)(s0 + d) * (DD / 4) + lane;
        float4* dst = myring + d * (DD / 4) + lane;
#pragma unroll
        for (int c = 0; c < 10; c++) cp_async16(dst + c * 32, src + c * 32);
        asm volatile("cp.async.commit_group;");
    }

    const int* mrow = mask + b * SS;

    __syncthreads();
    const float cb = scb;
    float4 kq[10];
#pragma unroll
    for (int c = 0; c < 10; c++)
        kq[c] = reinterpret_cast<const float4*>(skq)[c * 32 + lane];

    float m = -INFINITY, l = 0.0f;
    float4 acc[10];
#pragma unroll
    for (int c = 0; c < 10; c++) acc[c] = make_float4(0.f, 0.f, 0.f, 0.f);

    int slot = 0;
#pragma unroll 4
    for (int r = 0; r < RPW; r++) {
        asm volatile("cp.async.wait_group %0;" :: "n"(DEPTH - 1));

        // read row r from its slot (each lane reads only bytes it copied)
        float4 x[10];
        float4* buf = myring + slot * (DD / 4) + lane;
#pragma unroll
        for (int c = 0; c < 10; c++) x[c] = buf[c * 32];

        // refill this slot with row r+DEPTH (or commit an empty group to
        // keep the pending-group invariant exact at the tail)
        if (r + DEPTH < RPW) {
            const float4* src =
                base4 + (size_t)(s0 + r + DEPTH) * (DD / 4) + lane;
#pragma unroll
            for (int c = 0; c < 10; c++)
                cp_async16(buf + c * 32, src + c * 32);
        }
        asm volatile("cp.async.commit_group;");
        slot = (slot + 1 == DEPTH) ? 0 : slot + 1;

        // score
        float p = 0.0f;
#pragma unroll
        for (int c = 0; c < 10; c++) {
            p = fmaf(x[c].x, kq[c].x, p);
            p = fmaf(x[c].y, kq[c].y, p);
            p = fmaf(x[c].z, kq[c].z, p);
            p = fmaf(x[c].w, kq[c].w, p);
        }
#pragma unroll
        for (int off = 16; off > 0; off >>= 1)
            p += __shfl_xor_sync(0xffffffffu, p, off);

        float score = (p + cb) * scale;
        if (mrow[s0 + r] == 0) score = -1e9f;

        const float mn = fmaxf(m, score);
        if (mn > m) {
            const float fac = __expf(m - mn);
            l *= fac;
#pragma unroll
            for (int c = 0; c < 10; c++) {
                acc[c].x *= fac; acc[c].y *= fac;
                acc[c].z *= fac; acc[c].w *= fac;
            }
            m = mn;
        }
        const float w = __expf(score - m);
        l += w;
#pragma unroll
        for (int c = 0; c < 10; c++) {
            acc[c].x = fmaf(w, x[c].x, acc[c].x);
            acc[c].y = fmaf(w, x[c].y, acc[c].y);
            acc[c].z = fmaf(w, x[c].z, acc[c].z);
            acc[c].w = fmaf(w, x[c].w, acc[c].w);
        }
    }

    // ---- CTA-level merge of 4 warp partials -> 1 partial (R14-exact) ----
#pragma unroll
    for (int c = 0; c < 10; c++) sacc[warp * (DD / 4) + c * 32 + lane] = acc[c];
    if (lane == 0) { sm[warp] = m; sl[warp] = l; }
    __syncthreads();

    const float M = fmaxf(fmaxf(sm[0], sm[1]), fmaxf(sm[2], sm[3]));
    const float f0 = __expf(sm[0] - M), f1 = __expf(sm[1] - M);
    const float f2 = __expf(sm[2] - M), f3 = __expf(sm[3] - M);
    const float L = f0 * sl[0] + f1 * sl[1] + f2 * sl[2] + f3 * sl[3];

    const int pidx = b * NCP + cta;
    float4* pa = reinterpret_cast<float4*>(g_pacc + (size_t)pidx * DD);
#pragma unroll
    for (int i = 0; i < 3; i++) {
        const int idx = tid + i * 128;
        if (idx < DD / 4) {
            const float4 a0 = sacc[0 * (DD / 4) + idx];
            const float4 a1 = sacc[1 * (DD / 4) + idx];
            const float4 a2 = sacc[2 * (DD / 4) + idx];
            const float4 a3 = sacc[3 * (DD / 4) + idx];
            float4 s;
            s.x = fmaf(f0, a0.x, fmaf(f1, a1.x, fmaf(f2, a2.x, f3 * a3.x)));
            s.y = fmaf(f0, a0.y, fmaf(f1, a1.y, fmaf(f2, a2.y, f3 * a3.y)));
            s.z = fmaf(f0, a0.z, fmaf(f1, a1.z, fmaf(f2, a2.z, f3 * a3.z)));
            s.w = fmaf(f0, a0.w, fmaf(f1, a1.w, fmaf(f2, a2.w, f3 * a3.w)));
            pa[idx] = s;
        }
    }
    if (tid == 0) { g_pm[pidx] = M; g_pl[pidx] = L; }
}

// ---------------------------------------------------------------------------
// combine 16 CTA-partials -> pooled[b,:]. grid 32, block 320. (R14-exact)
// ---------------------------------------------------------------------------
__global__ void __launch_bounds__(320) combine_kernel()
{
    const int b = blockIdx.x;
    __shared__ float fs[NCP], ls[NCP];

    if (threadIdx.x < NCP) {
        float M = -INFINITY;
#pragma unroll
        for (int p = 0; p < NCP; p++) M = fmaxf(M, g_pm[b * NCP + p]);
        const float f = __expf(g_pm[b * NCP + threadIdx.x] - M);
        fs[threadIdx.x] = f;
        ls[threadIdx.x] = f * g_pl[b * NCP + threadIdx.x];
    }
    __syncthreads();

    float L = 0.0f;
#pragma unroll
    for (int p = 0; p < NCP; p++) L += ls[p];
    const float invL = 1.0f / L;

    const int d4 = threadIdx.x;   // 0..319
    float4 sum = make_float4(0.f, 0.f, 0.f, 0.f);
#pragma unroll
    for (int p = 0; p < NCP; p++) {
        const float f = fs[p];
        const float4 a = reinterpret_cast<const float4*>(
            g_pacc + (size_t)(b * NCP + p) * DD)[d4];
        sum.x = fmaf(f, a.x, sum.x);
        sum.y = fmaf(f, a.y, sum.y);
        sum.z = fmaf(f, a.z, sum.z);
        sum.w = fmaf(f, a.w, sum.w);
    }
    reinterpret_cast<float4*>(g_pooled + b * DD)[d4] =
        make_float4(sum.x * invL, sum.y * invL, sum.z * invL, sum.w * invL);
}

// ---------------------------------------------------------------------------
// LayerNorm + ReLU on g_h[32,1280] -> out. grid 32, block 320. (R14-exact)
// ---------------------------------------------------------------------------
__global__ void __launch_bounds__(320) ln_kernel(const float* __restrict__ gamma,
                                                 const float* __restrict__ beta,
                                                 float* __restrict__ out)
{
    const int b = blockIdx.x, tid = threadIdx.x;   // tid = float4 idx
    const int warp = tid >> 5, lane = tid & 31;

    const float4 s = reinterpret_cast<const float4*>(g_h)[b * (DD / 4) + tid];

    float sum = s.x + s.y + s.z + s.w;
    float sq  = s.x * s.x + s.y * s.y + s.z * s.z + s.w * s.w;
#pragma unroll
    for (int off = 16; off > 0; off >>= 1) {
        sum += __shfl_xor_sync(0xffffffffu, sum, off);
        sq  += __shfl_xor_sync(0xffffffffu, sq,  off);
    }
    __shared__ float rs[10], rq[10];
    __shared__ float smu, sinv;
    if (lane == 0) { rs[warp] = sum; rq[warp] = sq; }
    __syncthreads();
    if (tid == 0) {
        float S = 0.f, Q = 0.f;
#pragma unroll
        for (int w = 0; w < 10; w++) { S += rs[w]; Q += rq[w]; }
        const float mu = S * (1.0f / DD);
        float var = Q * (1.0f / DD) - mu * mu;
        var = fmaxf(var, 0.0f);
        smu = mu;
        sinv = rsqrtf(var + 1e-5f);
    }
    __syncthreads();
    const float mu = smu, inv = sinv;

    const float4 g  = reinterpret_cast<const float4*>(gamma)[tid];
    const float4 be = reinterpret_cast<const float4*>(beta)[tid];
    float4 o;
    o.x = fmaxf(fmaf((s.x - mu) * inv, g.x, be.x), 0.0f);
    o.y = fmaxf(fmaf((s.y - mu) * inv, g.y, be.y), 0.0f);
    o.z = fmaxf(fmaf((s.z - mu) * inv, g.z, be.z), 0.0f);
    o.w = fmaxf(fmaf((s.w - mu) * inv, g.w, be.w), 0.0f);
    reinterpret_cast<float4*>(out)[b * (DD / 4) + tid] = o;
}

// ---------------------------------------------------------------------------
extern "C" void kernel_launch(void* const* d_in, const int* in_sizes, int n_in,
                              void* d_out, int out_size)
{
    (void)in_sizes; (void)n_in; (void)out_size;

    const float* emb   = (const float*)d_in[0];
    const int*   mask  = (const int*)d_in[1];
    const float* Wq    = (const float*)d_in[2];
    const float* bq    = (const float*)d_in[3];
    const float* Wk    = (const float*)d_in[4];
    const float* bk    = (const float*)d_in[5];
    const float* Wv    = (const float*)d_in[6];
    const float* bv    = (const float*)d_in[7];
    const float* Wo    = (const float*)d_in[8];
    const float* bo    = (const float*)d_in[9];
    const float* gamma = (const float*)d_in[10];
    const float* beta  = (const float*)d_in[11];
    float* out = (float*)d_out;

    const float scale = 1.0f / sqrtf((float)DD);
    const dim3 ggrid(DD / 64, 32);   // 20 n-tiles x 32 k-splits = 640 CTAs

    static bool attr_set = false;
    if (!attr_set) {
        cudaFuncSetAttribute(attn_kernel,
                             cudaFuncAttributeMaxDynamicSharedMemorySize,
                             SMEM_ATTN);
        attr_set = true;
    }

    init_kernel<<<(BB * DD + 255) / 256, 256>>>(bq, bv, bo);
    gemm32<0, 0, 0><<<ggrid, 128>>>(emb, (size_t)SS * DD, Wq);     // q0
    gemm32<1, 1, 1><<<ggrid, 128>>>(nullptr, 0, Wk);               // kq = q0@Wk
    attn_kernel<<<BB * CTAS_PER_B, 128, SMEM_ATTN>>>(emb, mask, bk, scale);
    combine_kernel<<<BB, 320>>>();
    gemm32<0, 2, 2><<<ggrid, 128>>>(nullptr, 0, Wv);               // ctx
    gemm32<0, 3, 3><<<ggrid, 128>>>(nullptr, 0, Wo);               // h
    ln_kernel<<<BB, 320>>>(gamma, beta, out);
}